// round 14
// baseline (speedup 1.0000x reference)
#include <cuda_runtime.h>
#include <cuda_fp16.h>
#include <math.h>
#include <stdint.h>

#define NTOK 8192
#define DDIM 1024
#define HDIM 2048
#define MDIM 64
#define EEXP 8
#define HHALF 1024
#define ECAP 8192
#define NASSIGN (NTOK * 2)
#define S2C_SPLIT 16

// ---------------------------------------------------------------------------
// fp16 buffers: A-side natural half rows; B-side k-pair-packed half2 words
// ---------------------------------------------------------------------------
__device__ __half   g_Xh[(size_t)NTOK * DDIM];
__device__ uint32_t g_encWp[(size_t)(DDIM / 2) * HDIM];
__device__ uint32_t g_s2cWp[(size_t)(HDIM / 2) * MDIM];
__device__ uint32_t g_We1p[(size_t)EEXP * (MDIM / 2) * HHALF];
__device__ uint32_t g_We2p[(size_t)EEXP * (HHALF / 2) * MDIM];
__device__ uint32_t g_c2sWp[(size_t)(MDIM / 2) * HDIM];
__device__ uint32_t g_decWp[(size_t)(HDIM / 2) * DDIM];

__device__ float  g_part_s2c[(size_t)S2C_SPLIT * NTOK * MDIM];
__device__ __half g_cont[(size_t)NTOK * MDIM];
__device__ int    g_assign_e[NASSIGN];
__device__ float  g_assign_w[NASSIGN];
__device__ int    g_count[EEXP];
__device__ int    g_bucket[EEXP * ECAP];
__device__ float  g_part[(size_t)NASSIGN * MDIM];
__device__ __half g_outflat[(size_t)NTOK * MDIM];
__device__ __half g_spk_moe[(size_t)NTOK * HDIM];
__device__ float  g_decoded[(size_t)NTOK * DDIM];

__device__ __forceinline__ float sigf(float x) { return 1.0f / (1.0f + expf(-x)); }
__device__ __forceinline__ void cp16(void* dst, const void* src) {
    unsigned d = (unsigned)__cvta_generic_to_shared(dst);
    asm volatile("cp.async.cg.shared.global [%0], [%1], 16;\n" :: "r"(d), "l"(src));
}
__device__ __forceinline__ void cp_commit() { asm volatile("cp.async.commit_group;\n"); }
template<int N> __device__ __forceinline__ void cp_wait() {
    asm volatile("cp.async.wait_group %0;\n" :: "n"(N));
}
__device__ __forceinline__ void mma_f16(float c[4], const uint32_t a[4], const uint32_t b[2]) {
    asm volatile(
        "mma.sync.aligned.m16n8k16.row.col.f32.f16.f16.f32 "
        "{%0,%1,%2,%3}, {%4,%5,%6,%7}, {%8,%9}, {%0,%1,%2,%3};\n"
        : "+f"(c[0]), "+f"(c[1]), "+f"(c[2]), "+f"(c[3])
        : "r"(a[0]), "r"(a[1]), "r"(a[2]), "r"(a[3]), "r"(b[0]), "r"(b[1]));
}
__device__ __forceinline__ void ldsm_x4(uint32_t r[4], uint32_t saddr) {
    asm volatile("ldmatrix.sync.aligned.m8n8.x4.shared.b16 {%0,%1,%2,%3}, [%4];"
                 : "=r"(r[0]), "=r"(r[1]), "=r"(r[2]), "=r"(r[3]) : "r"(saddr));
}
__device__ __forceinline__ uint32_t smem_u32(const void* p) {
    return (uint32_t)__cvta_generic_to_shared(p);
}
__device__ __forceinline__ uint32_t h2u(float a, float b) {
    __half2 h = __floats2half2_rn(a, b);
    return *(uint32_t*)&h;
}

// GEMM geometry: BK=64 halfs (32 kp-words), 3 stages.
#define BM 128
#define BN 128
#define AS2 36
#define BS2 136
#define ST2 3
#define STG2_W (BM * AS2 + 32 * BS2)        // 8960 words / stage
#define PIPE2_SMEM (ST2 * STG2_W * 4)       // 107520 B
#define W2_S 72
#define SPIKE_S 68
#define SPIKE_OFF STG2_W

// Expert kernel smem layout (words)
#define EXA_OFF   0
#define EXW1_OFF  (128 * AS2)                     // 4608
#define EXW2_OFF  (EXW1_OFF + 2 * 32 * BS2)       // 13312
#define EXSPK_OFF (EXW2_OFF + 64 * W2_S)          // 17920
#define EX_SMEM   ((EXSPK_OFF + 128 * SPIKE_S) * 4)   // 106496 B

// ---------------------------------------------------------------------------
// Prep: X -> half; weights -> k-pair-packed half2 words.
// ---------------------------------------------------------------------------
#define PK_X   0UL
#define PK_EW  4194304UL
#define PK_SW  5242880UL
#define PK_W1  5308416UL
#define PK_W2  5570560UL
#define PK_CW  5832704UL
#define PK_DW  5898240UL
#define PK_TOT 6946816UL

__global__ void prep_all(const float* __restrict__ X,   const float* __restrict__ encW,
                         const float* __restrict__ s2cW, const float* __restrict__ We1,
                         const float* __restrict__ We2,  const float* __restrict__ c2sW,
                         const float* __restrict__ decW)
{
    if (blockIdx.x == 0 && threadIdx.x < EEXP) g_count[threadIdx.x] = 0;
    const size_t f = (size_t)blockIdx.x * 256 + threadIdx.x;
    if (f >= PK_TOT) return;
    if (f < PK_EW) {
        float2 v = *(const float2*)&X[2 * f];
        ((__half2*)g_Xh)[f] = __floats2half2_rn(v.x, v.y);
        return;
    }
    const float* src; uint32_t* dst; size_t local; int N;
    if      (f < PK_SW) { src = encW; dst = g_encWp; local = f - PK_EW; N = HDIM; }
    else if (f < PK_W1) { src = s2cW; dst = g_s2cWp; local = f - PK_SW; N = MDIM; }
    else if (f < PK_W2) { src = We1;  dst = g_We1p;  local = f - PK_W1; N = HHALF; }
    else if (f < PK_CW) { src = We2;  dst = g_We2p;  local = f - PK_W2; N = MDIM; }
    else if (f < PK_DW) { src = c2sW; dst = g_c2sWp; local = f - PK_CW; N = HDIM; }
    else                { src = decW; dst = g_decWp; local = f - PK_DW; N = DDIM; }
    const size_t kp = local / N, n = local % N;
    const float w0 = src[(2 * kp) * (size_t)N + n];
    const float w1 = src[(2 * kp + 1) * (size_t)N + n];
    ((__half2*)dst)[local] = __floats2half2_rn(w0, w1);
}

// ---------------------------------------------------------------------------
// Fused encoder+s2c GEMM+GEMM, fp16, BK=64 halfs, 3 stages, ldmatrix A.
// ---------------------------------------------------------------------------
__global__ __launch_bounds__(256, 2)
void enc_gemm2(const __half* __restrict__ A, const uint32_t* __restrict__ W1,
               const float* __restrict__ bb, const uint32_t* __restrict__ W2,
               float* __restrict__ Cpart, int K, int lda, int ldw1)
{
    extern __shared__ uint32_t smw[];
    uint32_t* w2s   = smw;               // stage-0 (dead after mainloop)
    uint32_t* spike = smw + SPIKE_OFF;   // stage-1

    const int tid = threadIdx.x, lane = tid & 31, w = tid >> 5;
    const int g = lane >> 2, tg = lane & 3;
    const int wm = w >> 2, wn = w & 3;
    const int rowsel = lane & 15;
    const int colsel = (lane >> 4) << 2;
    const int bm0 = blockIdx.y * BM, bn0 = blockIdx.x * BN;

    size_t aoff[4];
#pragma unroll
    for (int it = 0; it < 4; it++)
        aoff[it] = (size_t)(bm0 + (tid >> 3) + 32 * it) * lda;

    float c[4][4][4];
#pragma unroll
    for (int i = 0; i < 4; i++)
#pragma unroll
        for (int j = 0; j < 4; j++)
#pragma unroll
            for (int q = 0; q < 4; q++) c[i][j][q] = 0.0f;

    const int nk = K / 64;
    auto issue = [&](int st, int kt) {
        const int k0 = kt * 64;
        uint32_t* as = smw + st * STG2_W;
        uint32_t* bs = as + BM * AS2;
#pragma unroll
        for (int it = 0; it < 4; it++) {
            const int r  = (tid >> 3) + 32 * it;
            const int c4 = tid & 7;
            cp16(&as[r * AS2 + c4 * 4], A + aoff[it] + k0 + c4 * 8);
        }
#pragma unroll
        for (int it = 0; it < 4; it++) {
            int idx = tid + it * 256;
            int r = idx >> 5, cc = idx & 31;
            cp16(&bs[r * BS2 + cc * 4],
                 &W1[(size_t)(kt * 32 + r) * ldw1 + bn0 + cc * 4]);
        }
    };

#pragma unroll
    for (int s = 0; s < ST2 - 1; s++) {
        if (s < nk) issue(s, s);
        cp_commit();
    }
    for (int kt = 0; kt < nk; kt++) {
        cp_wait<ST2 - 2>();
        __syncthreads();
        const int st = kt % ST2;
        const uint32_t* bs = smw + st * STG2_W + BM * AS2;
        const uint32_t as_b = smem_u32(smw + st * STG2_W);
#pragma unroll
        for (int ks = 0; ks < 4; ks++) {
            uint32_t a[4][4], b[4][2];
#pragma unroll
            for (int mf = 0; mf < 4; mf++) {
                const int m0 = wm * 64 + mf * 16;
                ldsm_x4(a[mf], as_b + (((m0 + rowsel) * AS2 + ks * 8 + colsel) << 2));
            }
#pragma unroll
            for (int nf = 0; nf < 4; nf++) {
                const int n0 = wn * 32 + nf * 8 + g;
                b[nf][0] = bs[(ks * 8 + tg)     * BS2 + n0];
                b[nf][1] = bs[(ks * 8 + tg + 4) * BS2 + n0];
            }
#pragma unroll
            for (int mf = 0; mf < 4; mf++)
#pragma unroll
                for (int nf = 0; nf < 4; nf++) mma_f16(c[mf][nf], a[mf], b[nf]);
        }
        const int nxt = kt + ST2 - 1;
        if (nxt < nk) issue(nxt % ST2, nxt);
        cp_commit();
    }

    cp_wait<0>();
    __syncthreads();

    // Deferred W2 chunk into dead stage-0
#pragma unroll
    for (int it = 0; it < 4; it++) {
        int idx = tid + it * 256;
        int r = idx >> 4, cc = idx & 15;
        cp16(&w2s[r * W2_S + cc * 4], &W2[(size_t)(bn0 / 2 + r) * MDIM + cc * 4]);
    }
    cp_commit();

#pragma unroll
    for (int mf = 0; mf < 4; mf++)
#pragma unroll
        for (int nf = 0; nf < 4; nf++) {
            const int col = wn * 32 + nf * 8 + 2 * tg;
            const int r0  = wm * 64 + mf * 16 + g;
#pragma unroll
            for (int h = 0; h < 2; h++) {
                const int row = r0 + h * 8;
                float v0 = sigf(c[mf][nf][h * 2 + 0] + bb[bn0 + col]);
                float v1 = sigf(c[mf][nf][h * 2 + 1] + bb[bn0 + col + 1]);
                spike[row * SPIKE_S + (col >> 1)] = h2u(v0, v1);
            }
        }
    cp_wait<0>();
    __syncthreads();

    const int wm2 = w >> 1, wn2 = w & 1;
    const uint32_t spike_b = smem_u32(spike);
    float c2[2][4][4];
#pragma unroll
    for (int i = 0; i < 2; i++)
#pragma unroll
        for (int j = 0; j < 4; j++)
#pragma unroll
            for (int q = 0; q < 4; q++) c2[i][j][q] = 0.0f;
#pragma unroll
    for (int s = 0; s < 8; s++) {
        uint32_t a[2][4], b[4][2];
#pragma unroll
        for (int mf = 0; mf < 2; mf++) {
            const int m0 = wm2 * 32 + mf * 16;
            ldsm_x4(a[mf], spike_b + (((m0 + rowsel) * SPIKE_S + s * 8 + colsel) << 2));
        }
#pragma unroll
        for (int nf = 0; nf < 4; nf++) {
            const int n0 = wn2 * 32 + nf * 8 + g;
            b[nf][0] = w2s[(s * 8 + tg)     * W2_S + n0];
            b[nf][1] = w2s[(s * 8 + tg + 4) * W2_S + n0];
        }
#pragma unroll
        for (int mf = 0; mf < 2; mf++)
#pragma unroll
            for (int nf = 0; nf < 4; nf++) mma_f16(c2[mf][nf], a[mf], b[nf]);
    }
    const size_t sb = (size_t)blockIdx.x * NTOK * MDIM;
#pragma unroll
    for (int mf = 0; mf < 2; mf++)
#pragma unroll
        for (int nf = 0; nf < 4; nf++) {
            const int col = wn2 * 32 + nf * 8 + 2 * tg;
            const int r0  = wm2 * 32 + mf * 16 + g;
#pragma unroll
            for (int h = 0; h < 2; h++) {
                const int row = r0 + h * 8;
                *(float2*)&Cpart[sb + (size_t)(bm0 + row) * MDIM + col] =
                    make_float2(c2[mf][nf][h * 2 + 0], c2[mf][nf][h * 2 + 1]);
            }
        }
}

// ---------------------------------------------------------------------------
// Expert kernel: one CTA per (row-block, expert). A gathered ONCE; loop over
// 8 N-chunks (W1 double-buffered, W2 single); c2 accumulates across chunks.
// ---------------------------------------------------------------------------
__global__ __launch_bounds__(256, 2)
void expert_kernel(const __half* __restrict__ cont, const uint32_t* __restrict__ We1p,
                   const float* __restrict__ be1, const uint32_t* __restrict__ We2p,
                   float* __restrict__ part,
                   const int* __restrict__ bucket, const int* __restrict__ count)
{
    extern __shared__ uint32_t smw[];
    uint32_t* As    = smw + EXA_OFF;      // [128][AS2]
    uint32_t* w1s   = smw + EXW1_OFF;     // 2 x [32][BS2]
    uint32_t* w2s   = smw + EXW2_OFF;     // [64][W2_S]
    uint32_t* spike = smw + EXSPK_OFF;    // [128][SPIKE_S]

    const int tid = threadIdx.x, lane = tid & 31, w = tid >> 5;
    const int g = lane >> 2, tg = lane & 3;
    const int wm = w >> 2, wn = w & 3;
    const int rowsel = lane & 15;
    const int colsel = (lane >> 4) << 2;
    const int bm0 = blockIdx.x * BM;
    const int e   = blockIdx.y;

    const int cnt = count[e];
    if (bm0 >= cnt) return;

    const uint32_t* W1 = We1p + (size_t)e * (MDIM / 2) * HHALF;
    const float*    bb = be1 + (size_t)e * HHALF;
    const uint32_t* W2 = We2p + (size_t)e * (HHALF / 2) * MDIM;

    auto loadW1 = [&](int ch, int buf) {
        uint32_t* bs = w1s + buf * (32 * BS2);
#pragma unroll
        for (int it = 0; it < 4; it++) {
            int idx = tid + it * 256;
            int r = idx >> 5, cc = idx & 31;
            cp16(&bs[r * BS2 + cc * 4], &W1[(size_t)r * HHALF + ch * 128 + cc * 4]);
        }
    };
    auto loadW2 = [&](int ch) {
#pragma unroll
        for (int it = 0; it < 4; it++) {
            int idx = tid + it * 256;
            int r = idx >> 4, cc = idx & 15;
            cp16(&w2s[r * W2_S + cc * 4], &W2[(size_t)(ch * 64 + r) * MDIM + cc * 4]);
        }
    };

    // Gather A (128 rows x 32 words) + W1 chunk 0 -> group 0
#pragma unroll
    for (int it = 0; it < 4; it++) {
        int idx = tid + it * 256;
        int r = idx >> 3, c4 = idx & 7;
        const int grow = bm0 + r;
        const int rr = (grow < cnt) ? grow : (cnt - 1);
        const int tok = bucket[e * ECAP + rr] >> 1;
        cp16(&As[r * AS2 + c4 * 4], cont + (size_t)tok * MDIM + c4 * 8);
    }
    loadW1(0, 0);
    cp_commit();

    const uint32_t as_b = smem_u32(As);
    const uint32_t spike_b = smem_u32(spike);
    const int wm2 = w >> 1, wn2 = w & 1;

    float c2[2][4][4];
#pragma unroll
    for (int i = 0; i < 2; i++)
#pragma unroll
        for (int j = 0; j < 4; j++)
#pragma unroll
            for (int q = 0; q < 4; q++) c2[i][j][q] = 0.0f;

    for (int ch = 0; ch < 8; ch++) {
        // Issue W2[ch] and W1[ch+1]
        loadW2(ch);
        if (ch < 7) loadW1(ch + 1, (ch + 1) & 1);
        cp_commit();
        cp_wait<1>();          // A + W1[ch] ready
        __syncthreads();

        // GEMM1: c = A(128x64) @ W1chunk(64x128)
        const uint32_t* bs = w1s + (ch & 1) * (32 * BS2);
        float c[4][4][4];
#pragma unroll
        for (int i = 0; i < 4; i++)
#pragma unroll
            for (int j = 0; j < 4; j++)
#pragma unroll
                for (int q = 0; q < 4; q++) c[i][j][q] = 0.0f;
#pragma unroll
        for (int ks = 0; ks < 4; ks++) {
            uint32_t a[4][4], b[4][2];
#pragma unroll
            for (int mf = 0; mf < 4; mf++) {
                const int m0 = wm * 64 + mf * 16;
                ldsm_x4(a[mf], as_b + (((m0 + rowsel) * AS2 + ks * 8 + colsel) << 2));
            }
#pragma unroll
            for (int nf = 0; nf < 4; nf++) {
                const int n0 = wn * 32 + nf * 8 + g;
                b[nf][0] = bs[(ks * 8 + tg)     * BS2 + n0];
                b[nf][1] = bs[(ks * 8 + tg + 4) * BS2 + n0];
            }
#pragma unroll
            for (int mf = 0; mf < 4; mf++)
#pragma unroll
                for (int nf = 0; nf < 4; nf++) mma_f16(c[mf][nf], a[mf], b[nf]);
        }

        // relu(+bias) -> spike
#pragma unroll
        for (int mf = 0; mf < 4; mf++)
#pragma unroll
            for (int nf = 0; nf < 4; nf++) {
                const int col = wn * 32 + nf * 8 + 2 * tg;
                const int r0  = wm * 64 + mf * 16 + g;
#pragma unroll
                for (int h = 0; h < 2; h++) {
                    const int row = r0 + h * 8;
                    float v0 = fmaxf(c[mf][nf][h * 2 + 0] + bb[ch * 128 + col],     0.0f);
                    float v1 = fmaxf(c[mf][nf][h * 2 + 1] + bb[ch * 128 + col + 1], 0.0f);
                    spike[row * SPIKE_S + (col >> 1)] = h2u(v0, v1);
                }
            }
        cp_wait<0>();          // W2[ch] ready
        __syncthreads();

        // mini GEMM accumulate: c2 += spike(128x128) @ W2chunk(128x64)
#pragma unroll
        for (int s = 0; s < 8; s++) {
            uint32_t a[2][4], b[4][2];
#pragma unroll
            for (int mf = 0; mf < 2; mf++) {
                const int m0 = wm2 * 32 + mf * 16;
                ldsm_x4(a[mf], spike_b + (((m0 + rowsel) * SPIKE_S + s * 8 + colsel) << 2));
            }
#pragma unroll
            for (int nf = 0; nf < 4; nf++) {
                const int n0 = wn2 * 32 + nf * 8 + g;
                b[nf][0] = w2s[(s * 8 + tg)     * W2_S + n0];
                b[nf][1] = w2s[(s * 8 + tg + 4) * W2_S + n0];
            }
#pragma unroll
            for (int mf = 0; mf < 2; mf++)
#pragma unroll
                for (int nf = 0; nf < 4; nf++) mma_f16(c2[mf][nf], a[mf], b[nf]);
        }
        __syncthreads();       // spike & w2s free for next chunk
    }

    // Scatter unweighted per-assignment result
#pragma unroll
    for (int mf = 0; mf < 2; mf++)
#pragma unroll
        for (int nf = 0; nf < 4; nf++) {
            const int col = wn2 * 32 + nf * 8 + 2 * tg;
            const int r0  = wm2 * 32 + mf * 16 + g;
#pragma unroll
            for (int h = 0; h < 2; h++) {
                const int row = r0 + h * 8;
                if (bm0 + row < cnt) {
                    const int i = bucket[e * ECAP + bm0 + row];
                    *(float2*)&part[(size_t)i * MDIM + col] =
                        make_float2(c2[mf][nf][h * 2 + 0], c2[mf][nf][h * 2 + 1]);
                }
            }
        }
}

// ---------------------------------------------------------------------------
// Plain GEMM BK=64 halfs, 3 stages, ldmatrix A. MODE 0: dec. MODE 1: c2s.
// ---------------------------------------------------------------------------
template<int MODE>
__global__ __launch_bounds__(256, 2)
void mma_gemm(const __half* __restrict__ A, const uint32_t* __restrict__ Wp,
              const float* __restrict__ bias, void* __restrict__ Cv,
              int K, int Hout)
{
    extern __shared__ uint32_t smw[];
    const int tid = threadIdx.x, lane = tid & 31, w = tid >> 5;
    const int g = lane >> 2, tg = lane & 3;
    const int wm = w >> 2, wn = w & 3;
    const int rowsel = lane & 15;
    const int colsel = (lane >> 4) << 2;
    const int bm0 = blockIdx.y * BM, bn0 = blockIdx.x * BN;

    float c[4][4][4];
#pragma unroll
    for (int i = 0; i < 4; i++)
#pragma unroll
        for (int j = 0; j < 4; j++)
#pragma unroll
            for (int q = 0; q < 4; q++) c[i][j][q] = 0.0f;

    const int nk = K / 64;
    auto issue = [&](int st, int kt) {
        const int k0 = kt * 64;
        uint32_t* as = smw + st * STG2_W;
        uint32_t* bs = as + BM * AS2;
#pragma unroll
        for (int it = 0; it < 4; it++) {
            int idx = tid + it * 256;
            int r = idx >> 3, c4 = idx & 7;
            cp16(&as[r * AS2 + c4 * 4], A + (size_t)(bm0 + r) * K + k0 + c4 * 8);
        }
#pragma unroll
        for (int it = 0; it < 4; it++) {
            int idx = tid + it * 256;
            int r = idx >> 5, cc = idx & 31;
            cp16(&bs[r * BS2 + cc * 4],
                 &Wp[(size_t)(kt * 32 + r) * Hout + bn0 + cc * 4]);
        }
    };

#pragma unroll
    for (int s = 0; s < ST2 - 1; s++) {
        if (s < nk) issue(s, s);
        cp_commit();
    }
    for (int kt = 0; kt < nk; kt++) {
        cp_wait<ST2 - 2>();
        __syncthreads();
        const int st = kt % ST2;
        const uint32_t* bs = smw + st * STG2_W + BM * AS2;
        const uint32_t as_b = smem_u32(smw + st * STG2_W);
#pragma unroll
        for (int ks = 0; ks < 4; ks++) {
            uint32_t a[4][4], b[4][2];
#pragma unroll
            for (int mf = 0; mf < 4; mf++) {
                const int m0 = wm * 64 + mf * 16;
                ldsm_x4(a[mf], as_b + (((m0 + rowsel) * AS2 + ks * 8 + colsel) << 2));
            }
#pragma unroll
            for (int nf = 0; nf < 4; nf++) {
                const int n0 = wn * 32 + nf * 8 + g;
                b[nf][0] = bs[(ks * 8 + tg)     * BS2 + n0];
                b[nf][1] = bs[(ks * 8 + tg + 4) * BS2 + n0];
            }
#pragma unroll
            for (int mf = 0; mf < 4; mf++)
#pragma unroll
                for (int nf = 0; nf < 4; nf++) mma_f16(c[mf][nf], a[mf], b[nf]);
        }
        const int nxt = kt + ST2 - 1;
        if (nxt < nk) issue(nxt % ST2, nxt);
        cp_commit();
    }

#pragma unroll
    for (int mf = 0; mf < 4; mf++)
#pragma unroll
        for (int nf = 0; nf < 4; nf++) {
            const int col = bn0 + wn * 32 + nf * 8 + 2 * tg;
            const int r0  = bm0 + wm * 64 + mf * 16 + g;
#pragma unroll
            for (int h = 0; h < 2; h++) {
                const int row = r0 + h * 8;
                float v0 = sigf(c[mf][nf][h * 2 + 0] + bias[col]);
                float v1 = sigf(c[mf][nf][h * 2 + 1] + bias[col + 1]);
                if (MODE == 1) {
                    ((uint32_t*)Cv)[(size_t)row * (Hout / 2) + (col >> 1)] = h2u(v0, v1);
                } else {
                    *(float2*)&((float*)Cv)[(size_t)row * Hout + col] = make_float2(v0, v1);
                }
            }
        }
}

// ---------------------------------------------------------------------------
// Router: one warp per token, __syncwarp only.
// ---------------------------------------------------------------------------
__global__ void router_kernel(const float* __restrict__ part_s2c,
                              const float* __restrict__ s2c_b,
                              __half* __restrict__ cont,
                              const float* __restrict__ rW1, const float* __restrict__ rb1,
                              const float* __restrict__ rW2, const float* __restrict__ rb2,
                              int* __restrict__ assign_e, float* __restrict__ assign_w)
{
    __shared__ float cs[4][64], hid[4][64], logit[4][8];
    const int wid = threadIdx.x >> 5, lane = threadIdx.x & 31;
    const int n = blockIdx.x * 4 + wid;

#pragma unroll
    for (int j = 0; j < 2; j++) {
        const int t = lane + 32 * j;
        float cv = s2c_b[t];
#pragma unroll
        for (int s = 0; s < S2C_SPLIT; s++)
            cv += part_s2c[(size_t)s * NTOK * MDIM + (size_t)n * MDIM + t];
        cont[(size_t)n * MDIM + t] = __float2half_rn(cv);
        cs[wid][t] = cv;
    }
    __syncwarp();

#pragma unroll
    for (int j = 0; j < 2; j++) {
        const int t = lane + 32 * j;
        float a = rb1[t];
#pragma unroll
        for (int m = 0; m < 64; m++) a = fmaf(cs[wid][m], rW1[m * 64 + t], a);
        hid[wid][t] = tanhf(a);
    }
    __syncwarp();

    if (lane < EEXP) {
        float l = rb2[lane];
#pragma unroll
        for (int j = 0; j < 64; j++) l = fmaf(hid[wid][j], rW2[j * EEXP + lane], l);
        logit[wid][lane] = l;
    }
    __syncwarp();

    if (lane == 0) {
        float mx = logit[wid][0];
        for (int e = 1; e < EEXP; e++) mx = fmaxf(mx, logit[wid][e]);
        float p[EEXP];
        for (int e = 0; e < EEXP; e++) p[e] = expf(logit[wid][e] - mx);
        int i1 = 0;
        for (int e = 1; e < EEXP; e++) if (p[e] > p[i1]) i1 = e;
        int i2 = (i1 == 0) ? 1 : 0;
        for (int e = 0; e < EEXP; e++) if (e != i1 && p[e] > p[i2]) i2 = e;
        const float denom = p[i1] + p[i2];
        const int ids[2] = {i1, i2};
        const float ws[2] = {p[i1] / denom, p[i2] / denom};
#pragma unroll
        for (int k = 0; k < 2; k++) {
            const int i = n * 2 + k;
            assign_e[i] = ids[k];
            assign_w[i] = ws[k];
            const int slot = atomicAdd(&g_count[ids[k]], 1);
            g_bucket[ids[k] * ECAP + slot] = i;
        }
    }
}

__global__ void combine_kernel(const float* __restrict__ part,
                               const int* __restrict__ ae, const float* __restrict__ aw,
                               const float* __restrict__ be2, __half* __restrict__ outflat)
{
    const int i = blockIdx.x * 256 + threadIdx.x;
    const int n = i >> 6, m = i & 63;
    float acc = 0.0f;
#pragma unroll
    for (int k = 0; k < 2; k++) {
        const int idx = 2 * n + k;
        const float s = part[(size_t)idx * MDIM + m] + be2[ae[idx] * MDIM + m];
        acc = fmaf(aw[idx], s, acc);
    }
    outflat[i] = __float2half_rn(acc);
}

__global__ void layernorm_kernel(const float* __restrict__ x,
                                 const float* __restrict__ g, const float* __restrict__ b,
                                 float* __restrict__ out)
{
    const int n = blockIdx.x, t = threadIdx.x;
    const float* row = x + (size_t)n * DDIM;
    float v[4];
    float s = 0.0f, s2 = 0.0f;
#pragma unroll
    for (int i = 0; i < 4; i++) {
        v[i] = row[t + i * 256];
        s += v[i]; s2 += v[i] * v[i];
    }
#pragma unroll
    for (int o = 16; o > 0; o >>= 1) {
        s  += __shfl_xor_sync(0xFFFFFFFFu, s, o);
        s2 += __shfl_xor_sync(0xFFFFFFFFu, s2, o);
    }
    __shared__ float sh1[8], sh2[8], mu_s, rstd_s;
    const int warp = t >> 5, lane = t & 31;
    if (lane == 0) { sh1[warp] = s; sh2[warp] = s2; }
    __syncthreads();
    if (t == 0) {
        float S = 0.0f, S2 = 0.0f;
        for (int wq = 0; wq < 8; wq++) { S += sh1[wq]; S2 += sh2[wq]; }
        float mu = S / (float)DDIM;
        mu_s = mu;
        rstd_s = rsqrtf(S2 / (float)DDIM - mu * mu + 1e-5f);
    }
    __syncthreads();
    const float mu = mu_s, rstd = rstd_s;
    float* orow = out + (size_t)n * DDIM;
#pragma unroll
    for (int i = 0; i < 4; i++) {
        int col = t + i * 256;
        orow[col] = (v[i] - mu) * rstd * g[col] + b[col];
    }
}

// ---------------------------------------------------------------------------
extern "C" void kernel_launch(void* const* d_in, const int* in_sizes, int n_in,
                              void* d_out, int out_size)
{
    const float* X     = (const float*)d_in[0];
    const float* enc_W = (const float*)d_in[1];
    const float* enc_b = (const float*)d_in[2];
    const float* s2c_W = (const float*)d_in[3];
    const float* s2c_b = (const float*)d_in[4];
    const float* rW1   = (const float*)d_in[5];
    const float* rb1   = (const float*)d_in[6];
    const float* rW2   = (const float*)d_in[7];
    const float* rb2   = (const float*)d_in[8];
    const float* We1   = (const float*)d_in[9];
    const float* be1   = (const float*)d_in[10];
    const float* We2   = (const float*)d_in[11];
    const float* be2   = (const float*)d_in[12];
    const float* c2s_W = (const float*)d_in[13];
    const float* c2s_b = (const float*)d_in[14];
    const float* dec_W = (const float*)d_in[15];
    const float* dec_b = (const float*)d_in[16];
    const float* ln_g  = (const float*)d_in[17];
    const float* ln_b  = (const float*)d_in[18];

    __half *Xh, *cont, *outflat, *spk_moe;
    uint32_t *encWp, *s2cWp, *We1p, *We2p, *c2sWp, *decWp;
    float *part_s2c, *aw, *part, *decoded;
    int *ae, *bucket, *count;
    cudaGetSymbolAddress((void**)&Xh,       g_Xh);
    cudaGetSymbolAddress((void**)&encWp,    g_encWp);
    cudaGetSymbolAddress((void**)&s2cWp,    g_s2cWp);
    cudaGetSymbolAddress((void**)&We1p,     g_We1p);
    cudaGetSymbolAddress((void**)&We2p,     g_We2p);
    cudaGetSymbolAddress((void**)&c2sWp,    g_c2sWp);
    cudaGetSymbolAddress((void**)&decWp,    g_decWp);
    cudaGetSymbolAddress((void**)&part_s2c, g_part_s2c);
    cudaGetSymbolAddress((void**)&cont,     g_cont);
    cudaGetSymbolAddress((void**)&ae,       g_assign_e);
    cudaGetSymbolAddress((void**)&aw,       g_assign_w);
    cudaGetSymbolAddress((void**)&count,    g_count);
    cudaGetSymbolAddress((void**)&bucket,   g_bucket);
    cudaGetSymbolAddress((void**)&part,     g_part);
    cudaGetSymbolAddress((void**)&outflat,  g_outflat);
    cudaGetSymbolAddress((void**)&spk_moe,  g_spk_moe);
    cudaGetSymbolAddress((void**)&decoded,  g_decoded);

    auto kC2s = mma_gemm<1>;
    auto kDec = mma_gemm<0>;
    cudaFuncSetAttribute(enc_gemm2,     cudaFuncAttributeMaxDynamicSharedMemorySize, PIPE2_SMEM);
    cudaFuncSetAttribute(expert_kernel, cudaFuncAttributeMaxDynamicSharedMemorySize, EX_SMEM);
    cudaFuncSetAttribute(kC2s,          cudaFuncAttributeMaxDynamicSharedMemorySize, PIPE2_SMEM);
    cudaFuncSetAttribute(kDec,          cudaFuncAttributeMaxDynamicSharedMemorySize, PIPE2_SMEM);

    // 0) prep: fp16 conversion + k-pair packing + zero counts
    prep_all<<<(PK_TOT + 255) / 256, 256>>>(X, enc_W, s2c_W, We1, We2, c2s_W, dec_W);

    // 1) fused encoder+s2c (K=1024 halfs, 16 K-tiles)
    enc_gemm2<<<dim3(S2C_SPLIT, NTOK / BM), 256, PIPE2_SMEM>>>(
        Xh, encWp, enc_b, s2cWp, part_s2c, DDIM, DDIM, HDIM);

    // 2) routing (warp per token)
    router_kernel<<<NTOK / 4, 128>>>(part_s2c, s2c_b, cont, rW1, rb1, rW2, rb2, ae, aw);

    // 3) expert MLP: 1 CTA per (row-block, expert); chunks looped in-CTA
    expert_kernel<<<dim3(ECAP / BM, EEXP), 256, EX_SMEM>>>(
        cont, We1p, be1, We2p, part, bucket, count);

    // 4) combine (2 partials only)
    combine_kernel<<<(NTOK * MDIM) / 256, 256>>>(part, ae, aw, be2, outflat);

    // 5) c2s: sigmoid -> half spk_moe
    kC2s<<<dim3(HDIM / BN, NTOK / BM), 256, PIPE2_SMEM>>>(
        outflat, c2sWp, c2s_b, spk_moe, MDIM, HDIM);

    // 6) decoder: sigmoid -> fp32 decoded
    kDec<<<dim3(DDIM / BN, NTOK / BM), 256, PIPE2_SMEM>>>(
        spk_moe, decWp, dec_b, decoded, HDIM, DDIM);

    // 7) layernorm -> d_out
    layernorm_kernel<<<NTOK, 256>>>(decoded, ln_g, ln_b, (float*)d_out);
}

// round 15
// speedup vs baseline: 1.0348x; 1.0348x over previous
#include <cuda_runtime.h>
#include <cuda_fp16.h>
#include <math.h>
#include <stdint.h>

#define NTOK 8192
#define DDIM 1024
#define HDIM 2048
#define MDIM 64
#define EEXP 8
#define HHALF 1024
#define ECAP 8192
#define NASSIGN (NTOK * 2)
#define S2C_SPLIT 16
#define EXP_SPLIT 8

// ---------------------------------------------------------------------------
// fp16 buffers: A-side natural half rows; B-side k-pair-packed half2 words
// ---------------------------------------------------------------------------
__device__ __half   g_Xh[(size_t)NTOK * DDIM];
__device__ uint32_t g_encWp[(size_t)(DDIM / 2) * HDIM];
__device__ uint32_t g_s2cWp[(size_t)(HDIM / 2) * MDIM];
__device__ uint32_t g_We1p[(size_t)EEXP * (MDIM / 2) * HHALF];
__device__ uint32_t g_We2p[(size_t)EEXP * (HHALF / 2) * MDIM];
__device__ uint32_t g_c2sWp[(size_t)(MDIM / 2) * HDIM];
__device__ uint32_t g_decWp[(size_t)(HDIM / 2) * DDIM];

__device__ float  g_part_s2c[(size_t)S2C_SPLIT * NTOK * MDIM];
__device__ __half g_cont[(size_t)NTOK * MDIM];
__device__ int    g_assign_e[NASSIGN];
__device__ float  g_assign_w[NASSIGN];
__device__ int    g_count[EEXP];
__device__ int    g_bucket[EEXP * ECAP];
__device__ float  g_part_exp[(size_t)EXP_SPLIT * NASSIGN * MDIM];
__device__ __half g_outflat[(size_t)NTOK * MDIM];
__device__ __half g_spk_moe[(size_t)NTOK * HDIM];
__device__ float  g_decoded[(size_t)NTOK * DDIM];

__device__ __forceinline__ float sigf(float x) { return 1.0f / (1.0f + expf(-x)); }
__device__ __forceinline__ void cp16(void* dst, const void* src) {
    unsigned d = (unsigned)__cvta_generic_to_shared(dst);
    asm volatile("cp.async.cg.shared.global [%0], [%1], 16;\n" :: "r"(d), "l"(src));
}
__device__ __forceinline__ void cp_commit() { asm volatile("cp.async.commit_group;\n"); }
template<int N> __device__ __forceinline__ void cp_wait() {
    asm volatile("cp.async.wait_group %0;\n" :: "n"(N));
}
__device__ __forceinline__ void mma_f16(float c[4], const uint32_t a[4], const uint32_t b[2]) {
    asm volatile(
        "mma.sync.aligned.m16n8k16.row.col.f32.f16.f16.f32 "
        "{%0,%1,%2,%3}, {%4,%5,%6,%7}, {%8,%9}, {%0,%1,%2,%3};\n"
        : "+f"(c[0]), "+f"(c[1]), "+f"(c[2]), "+f"(c[3])
        : "r"(a[0]), "r"(a[1]), "r"(a[2]), "r"(a[3]), "r"(b[0]), "r"(b[1]));
}
__device__ __forceinline__ void ldsm_x4(uint32_t r[4], uint32_t saddr) {
    asm volatile("ldmatrix.sync.aligned.m8n8.x4.shared.b16 {%0,%1,%2,%3}, [%4];"
                 : "=r"(r[0]), "=r"(r[1]), "=r"(r[2]), "=r"(r[3]) : "r"(saddr));
}
__device__ __forceinline__ uint32_t smem_u32(const void* p) {
    return (uint32_t)__cvta_generic_to_shared(p);
}
__device__ __forceinline__ uint32_t h2u(float a, float b) {
    __half2 h = __floats2half2_rn(a, b);
    return *(uint32_t*)&h;
}

// Unified GEMM geometry: BK=64 halfs (32 kp-words), 3 stages.
#define BM 128
#define BN 128
#define AS2 36
#define BS2 136
#define ST2 3
#define STG2_W (BM * AS2 + 32 * BS2)        // 8960 words / stage
#define PIPE2_SMEM (ST2 * STG2_W * 4)       // 107520 B
#define W2_S 72
#define SPIKE_S 68
#define SPIKE_OFF STG2_W

// ---------------------------------------------------------------------------
// Prep: X -> half; weights -> k-pair-packed half2 words.
// ---------------------------------------------------------------------------
#define PK_X   0UL
#define PK_EW  4194304UL
#define PK_SW  5242880UL
#define PK_W1  5308416UL
#define PK_W2  5570560UL
#define PK_CW  5832704UL
#define PK_DW  5898240UL
#define PK_TOT 6946816UL

__global__ void prep_all(const float* __restrict__ X,   const float* __restrict__ encW,
                         const float* __restrict__ s2cW, const float* __restrict__ We1,
                         const float* __restrict__ We2,  const float* __restrict__ c2sW,
                         const float* __restrict__ decW)
{
    if (blockIdx.x == 0 && threadIdx.x < EEXP) g_count[threadIdx.x] = 0;
    const size_t f = (size_t)blockIdx.x * 256 + threadIdx.x;
    if (f >= PK_TOT) return;
    if (f < PK_EW) {
        float2 v = *(const float2*)&X[2 * f];
        ((__half2*)g_Xh)[f] = __floats2half2_rn(v.x, v.y);
        return;
    }
    const float* src; uint32_t* dst; size_t local; int N;
    if      (f < PK_SW) { src = encW; dst = g_encWp; local = f - PK_EW; N = HDIM; }
    else if (f < PK_W1) { src = s2cW; dst = g_s2cWp; local = f - PK_SW; N = MDIM; }
    else if (f < PK_W2) { src = We1;  dst = g_We1p;  local = f - PK_W1; N = HHALF; }
    else if (f < PK_CW) { src = We2;  dst = g_We2p;  local = f - PK_W2; N = MDIM; }
    else if (f < PK_DW) { src = c2sW; dst = g_c2sWp; local = f - PK_CW; N = HDIM; }
    else                { src = decW; dst = g_decWp; local = f - PK_DW; N = DDIM; }
    const size_t kp = local / N, n = local % N;
    const float w0 = src[(2 * kp) * (size_t)N + n];
    const float w1 = src[(2 * kp + 1) * (size_t)N + n];
    ((__half2*)dst)[local] = __floats2half2_rn(w0, w1);
}

// ---------------------------------------------------------------------------
// Fused GEMM+GEMM, fp16, BK=64 halfs, 3 stages, ldmatrix A, deferred W2.
//   EXPM=false: enc+s2c.   EXPM=true: expert MLP (gather/scatter).
// ---------------------------------------------------------------------------
template<bool EXPM>
__global__ __launch_bounds__(256, 2)
void fused_gemm2(const __half* __restrict__ A, const uint32_t* __restrict__ W1p,
                 const float* __restrict__ b1, const uint32_t* __restrict__ W2p,
                 float* __restrict__ Cpart, int K, int lda, int ldw1,
                 const int* __restrict__ bucket, const int* __restrict__ count)
{
    extern __shared__ uint32_t smw[];
    uint32_t* w2s   = smw;               // stage-0 region (dead after mainloop)
    uint32_t* spike = smw + SPIKE_OFF;   // stage-1 region

    const int tid = threadIdx.x, lane = tid & 31, w = tid >> 5;
    const int g = lane >> 2, tg = lane & 3;
    const int wm = w >> 2, wn = w & 3;
    const int rowsel = lane & 15;
    const int colsel = (lane >> 4) << 2;
    const int bm0 = blockIdx.y * BM, bn0 = blockIdx.x * BN;
    const int e = EXPM ? blockIdx.z : 0;

    int cnt = 0;
    if (EXPM) {
        cnt = count[e];
        if (bm0 >= cnt) return;
    }

    const uint32_t* W1 = EXPM ? W1p + (size_t)e * (MDIM / 2) * HHALF : W1p;
    const float*    bb = EXPM ? b1 + (size_t)e * HHALF : b1;
    const uint32_t* W2 = EXPM ? W2p + (size_t)e * (HHALF / 2) * MDIM : W2p;

    size_t aoff[4];
#pragma unroll
    for (int it = 0; it < 4; it++) {
        const int r = (tid >> 3) + 32 * it;
        const int grow = bm0 + r;
        if (EXPM) {
            const int rr = (grow < cnt) ? grow : (cnt - 1);
            aoff[it] = (size_t)(bucket[e * ECAP + rr] >> 1) * MDIM;
        } else {
            aoff[it] = (size_t)grow * lda;
        }
    }

    float c[4][4][4];
#pragma unroll
    for (int i = 0; i < 4; i++)
#pragma unroll
        for (int j = 0; j < 4; j++)
#pragma unroll
            for (int q = 0; q < 4; q++) c[i][j][q] = 0.0f;

    const int nk = K / 64;
    auto issue = [&](int st, int kt) {
        const int k0 = kt * 64;
        uint32_t* as = smw + st * STG2_W;
        uint32_t* bs = as + BM * AS2;
#pragma unroll
        for (int it = 0; it < 4; it++) {
            const int r  = (tid >> 3) + 32 * it;
            const int c4 = tid & 7;
            cp16(&as[r * AS2 + c4 * 4], A + aoff[it] + k0 + c4 * 8);
        }
#pragma unroll
        for (int it = 0; it < 4; it++) {
            int idx = tid + it * 256;
            int r = idx >> 5, cc = idx & 31;
            cp16(&bs[r * BS2 + cc * 4],
                 &W1[(size_t)(kt * 32 + r) * ldw1 + bn0 + cc * 4]);
        }
    };

#pragma unroll
    for (int s = 0; s < ST2 - 1; s++) {
        if (s < nk) issue(s, s);
        cp_commit();
    }
    for (int kt = 0; kt < nk; kt++) {
        cp_wait<ST2 - 2>();
        __syncthreads();
        const int st = kt % ST2;
        const uint32_t* bs = smw + st * STG2_W + BM * AS2;
        const uint32_t as_b = smem_u32(smw + st * STG2_W);
#pragma unroll
        for (int ks = 0; ks < 4; ks++) {
            uint32_t a[4][4], b[4][2];
#pragma unroll
            for (int mf = 0; mf < 4; mf++) {
                const int m0 = wm * 64 + mf * 16;
                ldsm_x4(a[mf], as_b + (((m0 + rowsel) * AS2 + ks * 8 + colsel) << 2));
            }
#pragma unroll
            for (int nf = 0; nf < 4; nf++) {
                const int n0 = wn * 32 + nf * 8 + g;
                b[nf][0] = bs[(ks * 8 + tg)     * BS2 + n0];
                b[nf][1] = bs[(ks * 8 + tg + 4) * BS2 + n0];
            }
#pragma unroll
            for (int mf = 0; mf < 4; mf++)
#pragma unroll
                for (int nf = 0; nf < 4; nf++) mma_f16(c[mf][nf], a[mf], b[nf]);
        }
        const int nxt = kt + ST2 - 1;
        if (nxt < nk) issue(nxt % ST2, nxt);
        cp_commit();
    }

    cp_wait<0>();
    __syncthreads();

    // Deferred W2 chunk into dead stage-0
#pragma unroll
    for (int it = 0; it < 4; it++) {
        int idx = tid + it * 256;
        int r = idx >> 4, cc = idx & 15;
        cp16(&w2s[r * W2_S + cc * 4], &W2[(size_t)(bn0 / 2 + r) * MDIM + cc * 4]);
    }
    cp_commit();

#pragma unroll
    for (int mf = 0; mf < 4; mf++)
#pragma unroll
        for (int nf = 0; nf < 4; nf++) {
            const int col = wn * 32 + nf * 8 + 2 * tg;
            const int r0  = wm * 64 + mf * 16 + g;
#pragma unroll
            for (int h = 0; h < 2; h++) {
                const int row = r0 + h * 8;
                float v0 = c[mf][nf][h * 2 + 0] + bb[bn0 + col];
                float v1 = c[mf][nf][h * 2 + 1] + bb[bn0 + col + 1];
                if (EXPM) { v0 = fmaxf(v0, 0.0f); v1 = fmaxf(v1, 0.0f); }
                else      { v0 = sigf(v0);        v1 = sigf(v1); }
                spike[row * SPIKE_S + (col >> 1)] = h2u(v0, v1);
            }
        }
    cp_wait<0>();
    __syncthreads();

    const int wm2 = w >> 1, wn2 = w & 1;
    const uint32_t spike_b = smem_u32(spike);
    float c2[2][4][4];
#pragma unroll
    for (int i = 0; i < 2; i++)
#pragma unroll
        for (int j = 0; j < 4; j++)
#pragma unroll
            for (int q = 0; q < 4; q++) c2[i][j][q] = 0.0f;
#pragma unroll
    for (int s = 0; s < 8; s++) {
        uint32_t a[2][4], b[4][2];
#pragma unroll
        for (int mf = 0; mf < 2; mf++) {
            const int m0 = wm2 * 32 + mf * 16;
            ldsm_x4(a[mf], spike_b + (((m0 + rowsel) * SPIKE_S + s * 8 + colsel) << 2));
        }
#pragma unroll
        for (int nf = 0; nf < 4; nf++) {
            const int n0 = wn2 * 32 + nf * 8 + g;
            b[nf][0] = w2s[(s * 8 + tg)     * W2_S + n0];
            b[nf][1] = w2s[(s * 8 + tg + 4) * W2_S + n0];
        }
#pragma unroll
        for (int mf = 0; mf < 2; mf++)
#pragma unroll
            for (int nf = 0; nf < 4; nf++) mma_f16(c2[mf][nf], a[mf], b[nf]);
    }
    const size_t sb = (size_t)blockIdx.x * (EXPM ? NASSIGN : NTOK) * MDIM;
#pragma unroll
    for (int mf = 0; mf < 2; mf++)
#pragma unroll
        for (int nf = 0; nf < 4; nf++) {
            const int col = wn2 * 32 + nf * 8 + 2 * tg;
            const int r0  = wm2 * 32 + mf * 16 + g;
#pragma unroll
            for (int h = 0; h < 2; h++) {
                const int row = r0 + h * 8;
                if (EXPM) {
                    if (bm0 + row < cnt) {
                        const int i = bucket[e * ECAP + bm0 + row];
                        *(float2*)&Cpart[sb + (size_t)i * MDIM + col] =
                            make_float2(c2[mf][nf][h * 2 + 0], c2[mf][nf][h * 2 + 1]);
                    }
                } else {
                    *(float2*)&Cpart[sb + (size_t)(bm0 + row) * MDIM + col] =
                        make_float2(c2[mf][nf][h * 2 + 0], c2[mf][nf][h * 2 + 1]);
                }
            }
        }
}

// ---------------------------------------------------------------------------
// Plain GEMM BK=64 halfs, 3 stages, ldmatrix A. MODE 0: dec. MODE 1: c2s.
// ---------------------------------------------------------------------------
template<int MODE>
__global__ __launch_bounds__(256, 2)
void mma_gemm(const __half* __restrict__ A, const uint32_t* __restrict__ Wp,
              const float* __restrict__ bias, void* __restrict__ Cv,
              int K, int Hout)
{
    extern __shared__ uint32_t smw[];
    const int tid = threadIdx.x, lane = tid & 31, w = tid >> 5;
    const int g = lane >> 2, tg = lane & 3;
    const int wm = w >> 2, wn = w & 3;
    const int rowsel = lane & 15;
    const int colsel = (lane >> 4) << 2;
    const int bm0 = blockIdx.y * BM, bn0 = blockIdx.x * BN;

    float c[4][4][4];
#pragma unroll
    for (int i = 0; i < 4; i++)
#pragma unroll
        for (int j = 0; j < 4; j++)
#pragma unroll
            for (int q = 0; q < 4; q++) c[i][j][q] = 0.0f;

    const int nk = K / 64;
    auto issue = [&](int st, int kt) {
        const int k0 = kt * 64;
        uint32_t* as = smw + st * STG2_W;
        uint32_t* bs = as + BM * AS2;
#pragma unroll
        for (int it = 0; it < 4; it++) {
            int idx = tid + it * 256;
            int r = idx >> 3, c4 = idx & 7;
            cp16(&as[r * AS2 + c4 * 4], A + (size_t)(bm0 + r) * K + k0 + c4 * 8);
        }
#pragma unroll
        for (int it = 0; it < 4; it++) {
            int idx = tid + it * 256;
            int r = idx >> 5, cc = idx & 31;
            cp16(&bs[r * BS2 + cc * 4],
                 &Wp[(size_t)(kt * 32 + r) * Hout + bn0 + cc * 4]);
        }
    };

#pragma unroll
    for (int s = 0; s < ST2 - 1; s++) {
        if (s < nk) issue(s, s);
        cp_commit();
    }
    for (int kt = 0; kt < nk; kt++) {
        cp_wait<ST2 - 2>();
        __syncthreads();
        const int st = kt % ST2;
        const uint32_t* bs = smw + st * STG2_W + BM * AS2;
        const uint32_t as_b = smem_u32(smw + st * STG2_W);
#pragma unroll
        for (int ks = 0; ks < 4; ks++) {
            uint32_t a[4][4], b[4][2];
#pragma unroll
            for (int mf = 0; mf < 4; mf++) {
                const int m0 = wm * 64 + mf * 16;
                ldsm_x4(a[mf], as_b + (((m0 + rowsel) * AS2 + ks * 8 + colsel) << 2));
            }
#pragma unroll
            for (int nf = 0; nf < 4; nf++) {
                const int n0 = wn * 32 + nf * 8 + g;
                b[nf][0] = bs[(ks * 8 + tg)     * BS2 + n0];
                b[nf][1] = bs[(ks * 8 + tg + 4) * BS2 + n0];
            }
#pragma unroll
            for (int mf = 0; mf < 4; mf++)
#pragma unroll
                for (int nf = 0; nf < 4; nf++) mma_f16(c[mf][nf], a[mf], b[nf]);
        }
        const int nxt = kt + ST2 - 1;
        if (nxt < nk) issue(nxt % ST2, nxt);
        cp_commit();
    }

#pragma unroll
    for (int mf = 0; mf < 4; mf++)
#pragma unroll
        for (int nf = 0; nf < 4; nf++) {
            const int col = bn0 + wn * 32 + nf * 8 + 2 * tg;
            const int r0  = bm0 + wm * 64 + mf * 16 + g;
#pragma unroll
            for (int h = 0; h < 2; h++) {
                const int row = r0 + h * 8;
                float v0 = sigf(c[mf][nf][h * 2 + 0] + bias[col]);
                float v1 = sigf(c[mf][nf][h * 2 + 1] + bias[col + 1]);
                if (MODE == 1) {
                    ((uint32_t*)Cv)[(size_t)row * (Hout / 2) + (col >> 1)] = h2u(v0, v1);
                } else {
                    *(float2*)&((float*)Cv)[(size_t)row * Hout + col] = make_float2(v0, v1);
                }
            }
        }
}

// ---------------------------------------------------------------------------
// Router: one warp per token, __syncwarp only (bit-same gates).
// ---------------------------------------------------------------------------
__global__ void router_kernel(const float* __restrict__ part_s2c,
                              const float* __restrict__ s2c_b,
                              __half* __restrict__ cont,
                              const float* __restrict__ rW1, const float* __restrict__ rb1,
                              const float* __restrict__ rW2, const float* __restrict__ rb2,
                              int* __restrict__ assign_e, float* __restrict__ assign_w)
{
    __shared__ float cs[4][64], hid[4][64], logit[4][8];
    const int wid = threadIdx.x >> 5, lane = threadIdx.x & 31;
    const int n = blockIdx.x * 4 + wid;

#pragma unroll
    for (int j = 0; j < 2; j++) {
        const int t = lane + 32 * j;
        float cv = s2c_b[t];
#pragma unroll
        for (int s = 0; s < S2C_SPLIT; s++)
            cv += part_s2c[(size_t)s * NTOK * MDIM + (size_t)n * MDIM + t];
        cont[(size_t)n * MDIM + t] = __float2half_rn(cv);
        cs[wid][t] = cv;
    }
    __syncwarp();

#pragma unroll
    for (int j = 0; j < 2; j++) {
        const int t = lane + 32 * j;
        float a = rb1[t];
#pragma unroll
        for (int m = 0; m < 64; m++) a = fmaf(cs[wid][m], rW1[m * 64 + t], a);
        hid[wid][t] = tanhf(a);
    }
    __syncwarp();

    if (lane < EEXP) {
        float l = rb2[lane];
#pragma unroll
        for (int j = 0; j < 64; j++) l = fmaf(hid[wid][j], rW2[j * EEXP + lane], l);
        logit[wid][lane] = l;
    }
    __syncwarp();

    if (lane == 0) {
        float mx = logit[wid][0];
        for (int e = 1; e < EEXP; e++) mx = fmaxf(mx, logit[wid][e]);
        float p[EEXP];
        for (int e = 0; e < EEXP; e++) p[e] = expf(logit[wid][e] - mx);
        int i1 = 0;
        for (int e = 1; e < EEXP; e++) if (p[e] > p[i1]) i1 = e;
        int i2 = (i1 == 0) ? 1 : 0;
        for (int e = 0; e < EEXP; e++) if (e != i1 && p[e] > p[i2]) i2 = e;
        const float denom = p[i1] + p[i2];
        const int ids[2] = {i1, i2};
        const float ws[2] = {p[i1] / denom, p[i2] / denom};
#pragma unroll
        for (int k = 0; k < 2; k++) {
            const int i = n * 2 + k;
            assign_e[i] = ids[k];
            assign_w[i] = ws[k];
            const int slot = atomicAdd(&g_count[ids[k]], 1);
            g_bucket[ids[k] * ECAP + slot] = i;
        }
    }
}

// Combine: vectorized, 2 cols/thread; per-element sum order identical to R13.
__global__ void combine_kernel(const float* __restrict__ part_exp,
                               const int* __restrict__ ae, const float* __restrict__ aw,
                               const float* __restrict__ be2, __half* __restrict__ outflat)
{
    const int i = blockIdx.x * 256 + threadIdx.x;   // over NTOK*32
    const int n = i >> 5, m2 = (i & 31) * 2;
    float acc0 = 0.0f, acc1 = 0.0f;
#pragma unroll
    for (int k = 0; k < 2; k++) {
        const int idx = 2 * n + k;
        float2 s = *(const float2*)&be2[ae[idx] * MDIM + m2];
#pragma unroll
        for (int sp = 0; sp < EXP_SPLIT; sp++) {
            float2 p = *(const float2*)&part_exp[(size_t)sp * NASSIGN * MDIM
                                                 + (size_t)idx * MDIM + m2];
            s.x += p.x; s.y += p.y;
        }
        acc0 = fmaf(aw[idx], s.x, acc0);
        acc1 = fmaf(aw[idx], s.y, acc1);
    }
    ((uint32_t*)outflat)[i] = h2u(acc0, acc1);
}

// LayerNorm: vectorized float4 load/store, one float4 per thread.
__global__ void layernorm_kernel(const float* __restrict__ x,
                                 const float* __restrict__ g, const float* __restrict__ b,
                                 float* __restrict__ out)
{
    const int n = blockIdx.x, t = threadIdx.x;
    const float4 v = *(const float4*)&x[(size_t)n * DDIM + t * 4];
    float s  = v.x + v.y + v.z + v.w;
    float s2 = v.x * v.x + v.y * v.y + v.z * v.z + v.w * v.w;
#pragma unroll
    for (int o = 16; o > 0; o >>= 1) {
        s  += __shfl_xor_sync(0xFFFFFFFFu, s, o);
        s2 += __shfl_xor_sync(0xFFFFFFFFu, s2, o);
    }
    __shared__ float sh1[8], sh2[8], mu_s, rstd_s;
    const int warp = t >> 5, lane = t & 31;
    if (lane == 0) { sh1[warp] = s; sh2[warp] = s2; }
    __syncthreads();
    if (t == 0) {
        float S = 0.0f, S2 = 0.0f;
        for (int wq = 0; wq < 8; wq++) { S += sh1[wq]; S2 += sh2[wq]; }
        float mu = S / (float)DDIM;
        mu_s = mu;
        rstd_s = rsqrtf(S2 / (float)DDIM - mu * mu + 1e-5f);
    }
    __syncthreads();
    const float mu = mu_s, rstd = rstd_s;
    const float4 gg = *(const float4*)&g[t * 4];
    const float4 bb = *(const float4*)&b[t * 4];
    float4 o;
    o.x = (v.x - mu) * rstd * gg.x + bb.x;
    o.y = (v.y - mu) * rstd * gg.y + bb.y;
    o.z = (v.z - mu) * rstd * gg.z + bb.z;
    o.w = (v.w - mu) * rstd * gg.w + bb.w;
    *(float4*)&out[(size_t)n * DDIM + t * 4] = o;
}

// ---------------------------------------------------------------------------
extern "C" void kernel_launch(void* const* d_in, const int* in_sizes, int n_in,
                              void* d_out, int out_size)
{
    const float* X     = (const float*)d_in[0];
    const float* enc_W = (const float*)d_in[1];
    const float* enc_b = (const float*)d_in[2];
    const float* s2c_W = (const float*)d_in[3];
    const float* s2c_b = (const float*)d_in[4];
    const float* rW1   = (const float*)d_in[5];
    const float* rb1   = (const float*)d_in[6];
    const float* rW2   = (const float*)d_in[7];
    const float* rb2   = (const float*)d_in[8];
    const float* We1   = (const float*)d_in[9];
    const float* be1   = (const float*)d_in[10];
    const float* We2   = (const float*)d_in[11];
    const float* be2   = (const float*)d_in[12];
    const float* c2s_W = (const float*)d_in[13];
    const float* c2s_b = (const float*)d_in[14];
    const float* dec_W = (const float*)d_in[15];
    const float* dec_b = (const float*)d_in[16];
    const float* ln_g  = (const float*)d_in[17];
    const float* ln_b  = (const float*)d_in[18];

    __half *Xh, *cont, *outflat, *spk_moe;
    uint32_t *encWp, *s2cWp, *We1p, *We2p, *c2sWp, *decWp;
    float *part_s2c, *aw, *part_exp, *decoded;
    int *ae, *bucket, *count;
    cudaGetSymbolAddress((void**)&Xh,       g_Xh);
    cudaGetSymbolAddress((void**)&encWp,    g_encWp);
    cudaGetSymbolAddress((void**)&s2cWp,    g_s2cWp);
    cudaGetSymbolAddress((void**)&We1p,     g_We1p);
    cudaGetSymbolAddress((void**)&We2p,     g_We2p);
    cudaGetSymbolAddress((void**)&c2sWp,    g_c2sWp);
    cudaGetSymbolAddress((void**)&decWp,    g_decWp);
    cudaGetSymbolAddress((void**)&part_s2c, g_part_s2c);
    cudaGetSymbolAddress((void**)&cont,     g_cont);
    cudaGetSymbolAddress((void**)&ae,       g_assign_e);
    cudaGetSymbolAddress((void**)&aw,       g_assign_w);
    cudaGetSymbolAddress((void**)&count,    g_count);
    cudaGetSymbolAddress((void**)&bucket,   g_bucket);
    cudaGetSymbolAddress((void**)&part_exp, g_part_exp);
    cudaGetSymbolAddress((void**)&outflat,  g_outflat);
    cudaGetSymbolAddress((void**)&spk_moe,  g_spk_moe);
    cudaGetSymbolAddress((void**)&decoded,  g_decoded);

    auto kEnc = fused_gemm2<false>;
    auto kExp = fused_gemm2<true>;
    auto kC2s = mma_gemm<1>;
    auto kDec = mma_gemm<0>;
    cudaFuncSetAttribute(kEnc, cudaFuncAttributeMaxDynamicSharedMemorySize, PIPE2_SMEM);
    cudaFuncSetAttribute(kExp, cudaFuncAttributeMaxDynamicSharedMemorySize, PIPE2_SMEM);
    cudaFuncSetAttribute(kC2s, cudaFuncAttributeMaxDynamicSharedMemorySize, PIPE2_SMEM);
    cudaFuncSetAttribute(kDec, cudaFuncAttributeMaxDynamicSharedMemorySize, PIPE2_SMEM);

    // 0) prep: fp16 conversion + k-pair packing + zero counts
    prep_all<<<(PK_TOT + 255) / 256, 256>>>(X, enc_W, s2c_W, We1, We2, c2s_W, dec_W);

    // 1) fused encoder+s2c (K=1024 halfs, 16 K-tiles)
    kEnc<<<dim3(S2C_SPLIT, NTOK / BM), 256, PIPE2_SMEM>>>(
        Xh, encWp, enc_b, s2cWp, part_s2c, DDIM, DDIM, HDIM, nullptr, nullptr);

    // 2) routing (warp per token)
    router_kernel<<<NTOK / 4, 128>>>(part_s2c, s2c_b, cont, rW1, rb1, rW2, rb2, ae, aw);

    // 3) fused expert MLP (K=64 halfs, single K-tile, split over N-chunks)
    kExp<<<dim3(EXP_SPLIT, ECAP / BM, EEXP), 256, PIPE2_SMEM>>>(
        cont, We1p, be1, We2p, part_exp, MDIM, MDIM, HHALF, bucket, count);

    // 4) combine (vectorized)
    combine_kernel<<<(NTOK * 32) / 256, 256>>>(part_exp, ae, aw, be2, outflat);

    // 5) c2s: sigmoid -> half spk_moe (K=64, single K-tile)
    kC2s<<<dim3(HDIM / BN, NTOK / BM), 256, PIPE2_SMEM>>>(
        outflat, c2sWp, c2s_b, spk_moe, MDIM, HDIM);

    // 6) decoder: sigmoid -> fp32 decoded (K=2048, 32 K-tiles)
    kDec<<<dim3(DDIM / BN, NTOK / BM), 256, PIPE2_SMEM>>>(
        spk_moe, decWp, dec_b, decoded, HDIM, DDIM);

    // 7) layernorm (vectorized) -> d_out
    layernorm_kernel<<<NTOK, 256>>>(decoded, ln_g, ln_b, (float*)d_out);
}